// round 10
// baseline (speedup 1.0000x reference)
#include <cuda_runtime.h>

#define B_POINTS 131072
#define HALF     65536
#define NSTEP    64
#define NTHREADS 128
#define NBLOCKS  1024     // 1024 * 128 = 131072 threads = 65536 point-pairs

typedef unsigned long long u64;

// ---- f32x2 packed helpers (sm_103a FFMA2 path, PTX-only) ----
__device__ __forceinline__ u64 f2fma(u64 a, u64 b, u64 c) {
    u64 d;
    asm("fma.rn.f32x2 %0, %1, %2, %3;" : "=l"(d) : "l"(a), "l"(b), "l"(c));
    return d;
}
__device__ __forceinline__ u64 pack2(float lo, float hi) {
    u64 d;
    asm("mov.b64 %0, {%1, %2};" : "=l"(d) : "f"(lo), "f"(hi));
    return d;
}
__device__ __forceinline__ void unpack2(u64 v, float& lo, float& hi) {
    asm("mov.b64 {%0, %1}, %2;" : "=f"(lo), "=f"(hi) : "l"(v));
}
__device__ __forceinline__ u64 f2relu(u64 v) {
    float lo, hi;
    unpack2(v, lo, hi);
    return pack2(fmaxf(lo, 0.0f), fmaxf(hi, 0.0f));   // FMNMX = alu pipe
}

__global__ __launch_bounds__(NTHREADS, 7)   // 896 thr/SM -> 72-reg budget, single wave
void ode_rk4_kernel(const float* __restrict__ x,
                    const float* __restrict__ samples,
                    const float* __restrict__ w1, const float* __restrict__ b1,
                    const float* __restrict__ w2, const float* __restrict__ b2,
                    const float* __restrict__ w3, const float* __restrict__ b3,
                    const float* __restrict__ w_out, const float* __restrict__ b_out,
                    float* __restrict__ out)
{
    // sw1v[i] = (w1[0][i], w1[1][i], w1[2][i], b1[i])   -- 1 LDS.128 per i
    // sw2v:  w2 row-major verbatim; ulonglong2 = 4 consecutive w2[i][j]
    // sb2b[j2] = (b2[2j2], b2[2j2+1])
    // sw3p[o*16+j2] = (w3[2j2][o], w3[2j2+1][o])        -- transposed pairs
    __shared__ float4     sw1v[32];
    __shared__ ulonglong2 sw2v[32 * 8];
    __shared__ u64        sb2b[16];
    __shared__ u64        sw3p[48];
    __shared__ float      sb3s[3];
    __shared__ float      swo[4];
    __shared__ float      sdt;
    __shared__ int        ssidx[8];

    const int t = threadIdx.x;

    for (int i4 = t; i4 < 128; i4 += NTHREADS) {
        int i = i4 >> 2, d = i4 & 3;
        ((float*)sw1v)[i4] = (d < 3) ? w1[d * 32 + i] : b1[i];
    }
    for (int i = t; i < 1024; i += NTHREADS)
        ((float*)sw2v)[i] = w2[i];
    if (t < 96) {
        int o = t >> 5, j = t & 31;
        ((float*)sw3p)[o * 32 + j] = w3[j * 3 + o];
    }
    if (t < 32) ((float*)sb2b)[t] = b2[t];
    if (t < 3)  { sb3s[t] = b3[t]; swo[t] = w_out[t]; }
    if (t == 3) swo[3] = b_out[0];
    if (t == 0) {
        float mx = samples[0];
        #pragma unroll
        for (int s = 1; s < 8; s++) mx = fmaxf(mx, samples[s]);
        sdt = mx / (float)NSTEP;
    }
    __syncthreads();
    if (t < 8) {
        int ii = (int)(rintf(samples[t] / sdt)) - 1;
        ssidx[t] = min(max(ii, 0), NSTEP - 1);
    }
    __syncthreads();

    u64 emit_mask = 0ull;
    #pragma unroll
    for (int s = 0; s < 8; s++) emit_mask |= 1ull << ssidx[s];

    const float dt  = sdt;
    const float hdt = 0.5f * dt;
    const float sx  = dt / 6.0f;
    const float bq0 = sb3s[0], bq1 = sb3s[1], bq2 = sb3s[2];

    const int half = t & 1;            // which 16 neurons this lane owns
    const int qb   = half * 4;         // w2 quad base
    const int j2b  = half * 8;         // layer-3 neuron-pair base

    const int pairidx = (blockIdx.x * NTHREADS + t) >> 1;
    const int p0 = pairidx, p1 = pairidx + HALF;

    float yA0 = x[p0 * 3 + 0], yA1 = x[p0 * 3 + 1], yA2 = x[p0 * 3 + 2];
    float yB0 = x[p1 * 3 + 0], yB1 = x[p1 * 3 + 1], yB2 = x[p1 * 3 + 2];

    // MLP 3->32->32->3 for two points; this lane owns neurons [16*half, 16*half+16).
    // Layer-1 duplicated across the lane pair (cheap); layer-2/3 split; partial
    // layer-3 sums combined with shfl.xor in canonical order (bit-identical lanes).
    auto mlp = [&](float aA0, float aA1, float aA2,
                   float aB0, float aB1, float aB2,
                   float& kA0, float& kA1, float& kA2,
                   float& kB0, float& kB1, float& kB2) {
        u64 hA[8], hB[8];
        #pragma unroll
        for (int m = 0; m < 8; m++) { u64 b = sb2b[j2b + m]; hA[m] = b; hB[m] = b; }
        #pragma unroll 2
        for (int i = 0; i < 32; i++) {
            float4 wv = sw1v[i];
            float h1A = wv.w;
            h1A = fmaf(aA0, wv.x, h1A);
            h1A = fmaf(aA1, wv.y, h1A);
            h1A = fmaf(aA2, wv.z, h1A);
            h1A = fmaxf(h1A, 0.0f);
            float h1B = wv.w;
            h1B = fmaf(aB0, wv.x, h1B);
            h1B = fmaf(aB1, wv.y, h1B);
            h1B = fmaf(aB2, wv.z, h1B);
            h1B = fmaxf(h1B, 0.0f);
            u64 dA = pack2(h1A, h1A);
            u64 dB = pack2(h1B, h1B);
            #pragma unroll
            for (int qq = 0; qq < 4; qq++) {
                ulonglong2 w = sw2v[i * 8 + qb + qq];
                hA[qq * 2]     = f2fma(dA, w.x, hA[qq * 2]);
                hA[qq * 2 + 1] = f2fma(dA, w.y, hA[qq * 2 + 1]);
                hB[qq * 2]     = f2fma(dB, w.x, hB[qq * 2]);
                hB[qq * 2 + 1] = f2fma(dB, w.y, hB[qq * 2 + 1]);
            }
        }
        u64 z = pack2(0.0f, 0.0f);
        u64 c0A = z, c1A = z, c2A = z, c0B = z, c1B = z, c2B = z;
        #pragma unroll
        for (int m = 0; m < 8; m++) {
            int j2 = j2b + m;
            u64 u0 = sw3p[j2];
            u64 u1 = sw3p[16 + j2];
            u64 u2 = sw3p[32 + j2];
            u64 rA = f2relu(hA[m]);
            u64 rB = f2relu(hB[m]);
            c0A = f2fma(rA, u0, c0A); c1A = f2fma(rA, u1, c1A); c2A = f2fma(rA, u2, c2A);
            c0B = f2fma(rB, u0, c0B); c1B = f2fma(rB, u1, c1B); c2B = f2fma(rB, u2, c2B);
        }
        // fold pair lanes of each c, then combine across the thread pair in
        // canonical (low-half first) order so both lanes get identical bits.
        float lo, hi;
        float pA0, pA1, pA2, pB0, pB1, pB2;
        unpack2(c0A, lo, hi); pA0 = lo + hi;
        unpack2(c1A, lo, hi); pA1 = lo + hi;
        unpack2(c2A, lo, hi); pA2 = lo + hi;
        unpack2(c0B, lo, hi); pB0 = lo + hi;
        unpack2(c1B, lo, hi); pB1 = lo + hi;
        unpack2(c2B, lo, hi); pB2 = lo + hi;
        float qA0 = __shfl_xor_sync(0xFFFFFFFFu, pA0, 1);
        float qA1 = __shfl_xor_sync(0xFFFFFFFFu, pA1, 1);
        float qA2 = __shfl_xor_sync(0xFFFFFFFFu, pA2, 1);
        float qB0 = __shfl_xor_sync(0xFFFFFFFFu, pB0, 1);
        float qB1 = __shfl_xor_sync(0xFFFFFFFFu, pB1, 1);
        float qB2 = __shfl_xor_sync(0xFFFFFFFFu, pB2, 1);
        // half==0 lane owns neurons 0..15 (low half)
        float l0 = half ? qA0 : pA0, h0 = half ? pA0 : qA0;
        float l1 = half ? qA1 : pA1, h1 = half ? pA1 : qA1;
        float l2 = half ? qA2 : pA2, h2 = half ? pA2 : qA2;
        kA0 = bq0 + l0 + h0; kA1 = bq1 + l1 + h1; kA2 = bq2 + l2 + h2;
        l0 = half ? qB0 : pB0; h0 = half ? pB0 : qB0;
        l1 = half ? qB1 : pB1; h1 = half ? pB1 : qB1;
        l2 = half ? qB2 : pB2; h2 = half ? pB2 : qB2;
        kB0 = bq0 + l0 + h0; kB1 = bq1 + l1 + h1; kB2 = bq2 + l2 + h2;
    };

    #pragma unroll 1
    for (int step = 0; step < NSTEP; step++) {
        float sA0 = 0.f, sA1 = 0.f, sA2 = 0.f;
        float sB0 = 0.f, sB1 = 0.f, sB2 = 0.f;
        float aA0 = yA0, aA1 = yA1, aA2 = yA2;
        float aB0 = yB0, aB1 = yB1, aB2 = yB2;

        #pragma unroll 1
        for (int st = 0; st < 4; st++) {
            float kA0, kA1, kA2, kB0, kB1, kB2;
            mlp(aA0, aA1, aA2, aB0, aB1, aB2, kA0, kA1, kA2, kB0, kB1, kB2);
            float cs = (st == 1 || st == 2) ? 2.0f : 1.0f;
            float ca = (st == 2) ? dt : hdt;
            sA0 = fmaf(kA0, cs, sA0); sA1 = fmaf(kA1, cs, sA1); sA2 = fmaf(kA2, cs, sA2);
            sB0 = fmaf(kB0, cs, sB0); sB1 = fmaf(kB1, cs, sB1); sB2 = fmaf(kB2, cs, sB2);
            aA0 = fmaf(kA0, ca, yA0); aA1 = fmaf(kA1, ca, yA1); aA2 = fmaf(kA2, ca, yA2);
            aB0 = fmaf(kB0, ca, yB0); aB1 = fmaf(kB1, ca, yB1); aB2 = fmaf(kB2, ca, yB2);
        }
        yA0 = fmaf(sA0, sx, yA0); yA1 = fmaf(sA1, sx, yA1); yA2 = fmaf(sA2, sx, yA2);
        yB0 = fmaf(sB0, sx, yB0); yB1 = fmaf(sB1, sx, yB1); yB2 = fmaf(sB2, sx, yB2);

        if ((emit_mask >> step) & 1ull) {
            if (half == 0) {
                float wo0 = swo[0], wo1 = swo[1], wo2 = swo[2], bo = swo[3];
                float oA = fmaf(yA0, wo0, fmaf(yA1, wo1, fmaf(yA2, wo2, bo)));
                float oB = fmaf(yB0, wo0, fmaf(yB1, wo1, fmaf(yB2, wo2, bo)));
                #pragma unroll 1
                for (int s = 0; s < 8; s++) {
                    if (ssidx[s] == step) {
                        out[s * B_POINTS + p0] = oA;
                        out[s * B_POINTS + p1] = oB;
                    }
                }
            }
        }
    }
}

extern "C" void kernel_launch(void* const* d_in, const int* in_sizes, int n_in,
                              void* d_out, int out_size)
{
    const float* x      = (const float*)d_in[0];
    const float* samples= (const float*)d_in[1];
    const float* w1     = (const float*)d_in[2];
    const float* b1     = (const float*)d_in[3];
    const float* w2     = (const float*)d_in[4];
    const float* b2     = (const float*)d_in[5];
    const float* w3     = (const float*)d_in[6];
    const float* b3     = (const float*)d_in[7];
    const float* w_out  = (const float*)d_in[8];
    const float* b_out  = (const float*)d_in[9];
    float* out = (float*)d_out;

    ode_rk4_kernel<<<NBLOCKS, NTHREADS>>>(x, samples, w1, b1, w2, b2, w3, b3,
                                          w_out, b_out, out);
}

// round 12
// speedup vs baseline: 1.5558x; 1.5558x over previous
#include <cuda_runtime.h>
#include <cstdint>

#define B_POINTS 131072
#define HALF     65536
#define NSTEP    64
#define NTHREADS 64
#define NBLOCKS  (HALF / NTHREADS)   // 1024

typedef unsigned long long u64;

// ---- f32x2 packed helpers (sm_103a FFMA2 path, PTX-only) ----
__device__ __forceinline__ u64 f2fma(u64 a, u64 b, u64 c) {
    u64 d;
    asm("fma.rn.f32x2 %0, %1, %2, %3;" : "=l"(d) : "l"(a), "l"(b), "l"(c));
    return d;
}
__device__ __forceinline__ u64 pack2(float lo, float hi) {
    u64 d;
    asm("mov.b64 %0, {%1, %2};" : "=l"(d) : "f"(lo), "f"(hi));
    return d;
}
__device__ __forceinline__ void unpack2(u64 v, float& lo, float& hi) {
    asm("mov.b64 {%0, %1}, %2;" : "=f"(lo), "=f"(hi) : "l"(v));
}
__device__ __forceinline__ u64 f2relu(u64 v) {
    float lo, hi;
    unpack2(v, lo, hi);
    return pack2(fmaxf(lo, 0.0f), fmaxf(hi, 0.0f));   // FMNMX = alu pipe
}

// ---- weight bundle: staged on device by prep kernel, memcpy'd into constant ----
struct CW {
    ulonglong2 w2v[32 * 8];   // w2 row-major verbatim: 4 consecutive w2[i][j] per ull2
    u64        w3p[48];       // [o*16+j2] = (w3[2j2][o], w3[2j2+1][o])
    u64        b2p[16];       // (b2[2j2], b2[2j2+1])
};
__device__   CW g_stage;
__constant__ CW cw;

__global__ void prep_kernel(const float* __restrict__ w2,
                            const float* __restrict__ b2,
                            const float* __restrict__ w3)
{
    const int t = threadIdx.x;   // 128 threads
    for (int i = t; i < 1024; i += 128)
        ((float*)g_stage.w2v)[i] = w2[i];
    if (t < 48) {
        int o = t / 16, j2 = t % 16;
        g_stage.w3p[o * 16 + j2] = pack2(w3[(2 * j2) * 3 + o], w3[(2 * j2 + 1) * 3 + o]);
    }
    if (t < 16)
        g_stage.b2p[t] = pack2(b2[2 * t], b2[2 * t + 1]);
}

__global__ __launch_bounds__(NTHREADS, 7)   // 146-reg budget; grid fills only 6.92/SM
void ode_rk4_kernel(const float* __restrict__ x,
                    const float* __restrict__ samples,
                    const float* __restrict__ w1, const float* __restrict__ b1,
                    const float* __restrict__ b3,
                    const float* __restrict__ w_out, const float* __restrict__ b_out,
                    float* __restrict__ out)
{
    // Only layer-1 stays in shared (parallel port to the constant bank).
    __shared__ float4 sw1v[32];   // (w1[0][i], w1[1][i], w1[2][i], b1[i])
    __shared__ float  sb3s[3];
    __shared__ float  swo[4];
    __shared__ float  sdt;
    __shared__ int    ssidx[8];

    const int t = threadIdx.x;

    for (int i4 = t; i4 < 128; i4 += NTHREADS) {
        int i = i4 >> 2, d = i4 & 3;
        ((float*)sw1v)[i4] = (d < 3) ? w1[d * 32 + i] : b1[i];
    }
    if (t < 3)  { sb3s[t] = b3[t]; swo[t] = w_out[t]; }
    if (t == 3) swo[3] = b_out[0];
    if (t == 0) {
        float mx = samples[0];
        #pragma unroll
        for (int s = 1; s < 8; s++) mx = fmaxf(mx, samples[s]);
        sdt = mx / (float)NSTEP;
    }
    __syncthreads();
    if (t < 8) {
        int ii = (int)(rintf(samples[t] / sdt)) - 1;
        ssidx[t] = min(max(ii, 0), NSTEP - 1);
    }
    __syncthreads();

    u64 emit_mask = 0ull;
    #pragma unroll
    for (int s = 0; s < 8; s++) emit_mask |= 1ull << ssidx[s];

    const float dt  = sdt;
    const float hdt = 0.5f * dt;
    const float sx  = dt / 6.0f;
    const float wo0 = swo[0], wo1 = swo[1], wo2 = swo[2], bo = swo[3];
    const float bq0 = sb3s[0], bq1 = sb3s[1], bq2 = sb3s[2];

    const int g  = blockIdx.x * NTHREADS + t;
    const int p0 = g, p1 = g + HALF;

    float yA0 = x[p0 * 3 + 0], yA1 = x[p0 * 3 + 1], yA2 = x[p0 * 3 + 2];
    float yB0 = x[p1 * 3 + 0], yB1 = x[p1 * 3 + 1], yB2 = x[p1 * 3 + 2];

    // MLP 3->32->32->3 for two points. Layer-1 weights via shared (LDS.128),
    // layer-2/3 weights via the constant port (uniform LDCU) — parallel paths.
    auto mlp = [&](float aA0, float aA1, float aA2,
                   float aB0, float aB1, float aB2,
                   float& kA0, float& kA1, float& kA2,
                   float& kB0, float& kB1, float& kB2) {
        u64 hA[16], hB[16];
        #pragma unroll
        for (int m = 0; m < 16; m++) {
            u64 b = cw.b2p[m];
            hA[m] = b; hB[m] = b;
        }
        #pragma unroll 8
        for (int i = 0; i < 32; i++) {
            float4 wv = sw1v[i];
            float h1A = wv.w;
            h1A = fmaf(aA0, wv.x, h1A);
            h1A = fmaf(aA1, wv.y, h1A);
            h1A = fmaf(aA2, wv.z, h1A);
            h1A = fmaxf(h1A, 0.0f);
            float h1B = wv.w;
            h1B = fmaf(aB0, wv.x, h1B);
            h1B = fmaf(aB1, wv.y, h1B);
            h1B = fmaf(aB2, wv.z, h1B);
            h1B = fmaxf(h1B, 0.0f);
            u64 dA = pack2(h1A, h1A);
            u64 dB = pack2(h1B, h1B);
            #pragma unroll
            for (int q = 0; q < 8; q++) {
                ulonglong2 w = cw.w2v[i * 8 + q];
                hA[q * 2]     = f2fma(dA, w.x, hA[q * 2]);
                hA[q * 2 + 1] = f2fma(dA, w.y, hA[q * 2 + 1]);
                hB[q * 2]     = f2fma(dB, w.x, hB[q * 2]);
                hB[q * 2 + 1] = f2fma(dB, w.y, hB[q * 2 + 1]);
            }
        }
        u64 z = pack2(0.0f, 0.0f);
        u64 c0A = z, c1A = z, c2A = z, c0B = z, c1B = z, c2B = z;
        #pragma unroll
        for (int j2 = 0; j2 < 16; j2++) {
            u64 u0 = cw.w3p[j2];
            u64 u1 = cw.w3p[16 + j2];
            u64 u2 = cw.w3p[32 + j2];
            u64 rA = f2relu(hA[j2]);
            u64 rB = f2relu(hB[j2]);
            c0A = f2fma(rA, u0, c0A); c1A = f2fma(rA, u1, c1A); c2A = f2fma(rA, u2, c2A);
            c0B = f2fma(rB, u0, c0B); c1B = f2fma(rB, u1, c1B); c2B = f2fma(rB, u2, c2B);
        }
        float lo, hi;
        unpack2(c0A, lo, hi); kA0 = bq0 + lo + hi;
        unpack2(c1A, lo, hi); kA1 = bq1 + lo + hi;
        unpack2(c2A, lo, hi); kA2 = bq2 + lo + hi;
        unpack2(c0B, lo, hi); kB0 = bq0 + lo + hi;
        unpack2(c1B, lo, hi); kB1 = bq1 + lo + hi;
        unpack2(c2B, lo, hi); kB2 = bq2 + lo + hi;
    };

    #pragma unroll 1
    for (int step = 0; step < NSTEP; step++) {
        float sA0 = 0.f, sA1 = 0.f, sA2 = 0.f;
        float sB0 = 0.f, sB1 = 0.f, sB2 = 0.f;
        float aA0 = yA0, aA1 = yA1, aA2 = yA2;
        float aB0 = yB0, aB1 = yB1, aB2 = yB2;

        #pragma unroll 1
        for (int st = 0; st < 4; st++) {
            float kA0, kA1, kA2, kB0, kB1, kB2;
            mlp(aA0, aA1, aA2, aB0, aB1, aB2, kA0, kA1, kA2, kB0, kB1, kB2);
            float cs = (st == 1 || st == 2) ? 2.0f : 1.0f;
            float ca = (st == 2) ? dt : hdt;
            sA0 = fmaf(kA0, cs, sA0); sA1 = fmaf(kA1, cs, sA1); sA2 = fmaf(kA2, cs, sA2);
            sB0 = fmaf(kB0, cs, sB0); sB1 = fmaf(kB1, cs, sB1); sB2 = fmaf(kB2, cs, sB2);
            aA0 = fmaf(kA0, ca, yA0); aA1 = fmaf(kA1, ca, yA1); aA2 = fmaf(kA2, ca, yA2);
            aB0 = fmaf(kB0, ca, yB0); aB1 = fmaf(kB1, ca, yB1); aB2 = fmaf(kB2, ca, yB2);
        }
        yA0 = fmaf(sA0, sx, yA0); yA1 = fmaf(sA1, sx, yA1); yA2 = fmaf(sA2, sx, yA2);
        yB0 = fmaf(sB0, sx, yB0); yB1 = fmaf(sB1, sx, yB1); yB2 = fmaf(sB2, sx, yB2);

        if ((emit_mask >> step) & 1ull) {
            float oA = fmaf(yA0, wo0, fmaf(yA1, wo1, fmaf(yA2, wo2, bo)));
            float oB = fmaf(yB0, wo0, fmaf(yB1, wo1, fmaf(yB2, wo2, bo)));
            #pragma unroll 1
            for (int s = 0; s < 8; s++) {
                if (ssidx[s] == step) {
                    out[s * B_POINTS + p0] = oA;
                    out[s * B_POINTS + p1] = oB;
                }
            }
        }
    }
}

extern "C" void kernel_launch(void* const* d_in, const int* in_sizes, int n_in,
                              void* d_out, int out_size)
{
    const float* x      = (const float*)d_in[0];
    const float* samples= (const float*)d_in[1];
    const float* w1     = (const float*)d_in[2];
    const float* b1     = (const float*)d_in[3];
    const float* w2     = (const float*)d_in[4];
    const float* b2     = (const float*)d_in[5];
    const float* w3     = (const float*)d_in[6];
    const float* b3     = (const float*)d_in[7];
    const float* w_out  = (const float*)d_in[8];
    const float* b_out  = (const float*)d_in[9];
    float* out = (float*)d_out;

    // Stage transformed weights, then copy into __constant__ (D2D, capturable).
    prep_kernel<<<1, 128>>>(w2, b2, w3);
    void* stage_addr = nullptr;
    cudaGetSymbolAddress(&stage_addr, g_stage);
    cudaMemcpyToSymbolAsync(cw, stage_addr, sizeof(CW), 0,
                            cudaMemcpyDeviceToDevice, 0);

    ode_rk4_kernel<<<NBLOCKS, NTHREADS>>>(x, samples, w1, b1,
                                          b3, w_out, b_out, out);
}

// round 14
// speedup vs baseline: 1.5846x; 1.0185x over previous
#include <cuda_runtime.h>
#include <cstdint>

#define B_POINTS 131072
#define NSTEP    64
#define NTHREADS 128
#define NBLOCKS  (B_POINTS / NTHREADS)   // 1024

typedef unsigned long long u64;

// ---- f32x2 packed helpers (sm_103a FFMA2 path, PTX-only) ----
__device__ __forceinline__ u64 f2fma(u64 a, u64 b, u64 c) {
    u64 d;
    asm("fma.rn.f32x2 %0, %1, %2, %3;" : "=l"(d) : "l"(a), "l"(b), "l"(c));
    return d;
}
__device__ __forceinline__ u64 pack2(float lo, float hi) {
    u64 d;
    asm("mov.b64 %0, {%1, %2};" : "=l"(d) : "f"(lo), "f"(hi));
    return d;
}
__device__ __forceinline__ void unpack2(u64 v, float& lo, float& hi) {
    asm("mov.b64 {%0, %1}, %2;" : "=f"(lo), "=f"(hi) : "l"(v));
}
__device__ __forceinline__ u64 f2relu(u64 v) {
    float lo, hi;
    unpack2(v, lo, hi);
    return pack2(fmaxf(lo, 0.0f), fmaxf(hi, 0.0f));   // FMNMX = alu pipe
}

// ---- constant bundle: w2 low half (outputs 0..15), w3 pairs, b2 pairs ----
struct CW {
    ulonglong2 w2lo[32 * 4];  // [i*4+q] = floats w2[i][4q..4q+3], q=0..3
    u64        w3p[48];       // [o*16+m] = (w3[2m][o], w3[2m+1][o])
    u64        b2p[16];       // (b2[2m], b2[2m+1])
};
__device__   CW g_stage;
__constant__ CW cw;

__global__ void prep_kernel(const float* __restrict__ w2,
                            const float* __restrict__ b2,
                            const float* __restrict__ w3)
{
    const int t = threadIdx.x;   // 128 threads
    for (int idx = t; idx < 512; idx += 128) {
        int i = idx >> 4, r = idx & 15;
        ((float*)g_stage.w2lo)[idx] = w2[i * 32 + r];
    }
    if (t < 48) {
        int o = t / 16, m = t % 16;
        g_stage.w3p[o * 16 + m] = pack2(w3[(2 * m) * 3 + o], w3[(2 * m + 1) * 3 + o]);
    }
    if (t < 16)
        g_stage.b2p[t] = pack2(b2[2 * t], b2[2 * t + 1]);
}

__global__ __launch_bounds__(NTHREADS, 6)   // 768 thr/SM cap -> 85-reg budget
void ode_rk4_kernel(const float* __restrict__ x,
                    const float* __restrict__ samples,
                    const float* __restrict__ w1, const float* __restrict__ b1,
                    const float* __restrict__ w2, const float* __restrict__ b3,
                    const float* __restrict__ w_out, const float* __restrict__ b_out,
                    float* __restrict__ out)
{
    // smem: w2 high half (outputs 16..31) + layer-1 neuron-pair weights.
    __shared__ ulonglong2 sw2hi[32 * 4];  // [i*4+q] = floats w2[i][16+4q .. 16+4q+3]
    __shared__ u64        sw1p[64];       // [m*4+d] = (w1[d][2m], w1[d][2m+1]); d=3 -> b1 pair
    __shared__ float      sb3s[3];
    __shared__ float      swo[4];
    __shared__ float      sdt;
    __shared__ int        ssidx[8];

    const int t = threadIdx.x;

    for (int idx = t; idx < 512; idx += NTHREADS) {
        int i = idx >> 4, r = idx & 15;
        ((float*)sw2hi)[idx] = w2[i * 32 + 16 + r];
    }
    if (t < 16) {
        sw1p[t * 4 + 0] = pack2(w1[0 * 32 + 2 * t], w1[0 * 32 + 2 * t + 1]);
        sw1p[t * 4 + 1] = pack2(w1[1 * 32 + 2 * t], w1[1 * 32 + 2 * t + 1]);
        sw1p[t * 4 + 2] = pack2(w1[2 * 32 + 2 * t], w1[2 * 32 + 2 * t + 1]);
        sw1p[t * 4 + 3] = pack2(b1[2 * t], b1[2 * t + 1]);
    }
    if (t >= 32 && t < 35) { sb3s[t - 32] = b3[t - 32]; swo[t - 32] = w_out[t - 32]; }
    if (t == 35) swo[3] = b_out[0];
    if (t == 36) {
        float mx = samples[0];
        #pragma unroll
        for (int s = 1; s < 8; s++) mx = fmaxf(mx, samples[s]);
        sdt = mx / (float)NSTEP;
    }
    __syncthreads();
    if (t < 8) {
        int ii = (int)(rintf(samples[t] / sdt)) - 1;
        ssidx[t] = min(max(ii, 0), NSTEP - 1);
    }
    __syncthreads();

    u64 emit_mask = 0ull;
    #pragma unroll
    for (int s = 0; s < 8; s++) emit_mask |= 1ull << ssidx[s];

    const float dt  = sdt;
    const float hdt = 0.5f * dt;
    const float sx  = dt / 6.0f;
    const float wo0 = swo[0], wo1 = swo[1], wo2 = swo[2], bo = swo[3];
    const float bq0 = sb3s[0], bq1 = sb3s[1], bq2 = sb3s[2];

    const int p = blockIdx.x * NTHREADS + t;   // 1 point per thread
    float y0 = x[p * 3 + 0], y1 = x[p * 3 + 1], y2 = x[p * 3 + 2];

    // MLP 3->32->32->3 for ONE point.
    // L1 packed over neuron pairs (smem); L2 split: outputs 0..15 via constant
    // port, outputs 16..31 via smem port (parallel paths); L3 via constant.
    auto mlp = [&](float a0, float a1, float a2,
                   float& k0, float& k1, float& k2) {
        u64 ad0 = pack2(a0, a0), ad1 = pack2(a1, a1), ad2 = pack2(a2, a2);
        u64 h[16];
        #pragma unroll
        for (int m = 0; m < 16; m++) h[m] = cw.b2p[m];
        #pragma unroll 4
        for (int m = 0; m < 16; m++) {       // neuron pair (2m, 2m+1)
            u64 hp = f2fma(ad2, sw1p[m * 4 + 2], sw1p[m * 4 + 3]);
            hp = f2fma(ad1, sw1p[m * 4 + 1], hp);
            hp = f2fma(ad0, sw1p[m * 4 + 0], hp);
            float e0, e1;
            unpack2(hp, e0, e1);
            e0 = fmaxf(e0, 0.0f);
            e1 = fmaxf(e1, 0.0f);
            u64 d0 = pack2(e0, e0), d1 = pack2(e1, e1);
            #pragma unroll
            for (int q = 0; q < 4; q++) {    // neuron i = 2m
                ulonglong2 wc = cw.w2lo[(2 * m) * 4 + q];
                ulonglong2 ws = sw2hi[(2 * m) * 4 + q];
                h[2 * q]         = f2fma(d0, wc.x, h[2 * q]);
                h[2 * q + 1]     = f2fma(d0, wc.y, h[2 * q + 1]);
                h[8 + 2 * q]     = f2fma(d0, ws.x, h[8 + 2 * q]);
                h[8 + 2 * q + 1] = f2fma(d0, ws.y, h[8 + 2 * q + 1]);
            }
            #pragma unroll
            for (int q = 0; q < 4; q++) {    // neuron i = 2m+1
                ulonglong2 wc = cw.w2lo[(2 * m + 1) * 4 + q];
                ulonglong2 ws = sw2hi[(2 * m + 1) * 4 + q];
                h[2 * q]         = f2fma(d1, wc.x, h[2 * q]);
                h[2 * q + 1]     = f2fma(d1, wc.y, h[2 * q + 1]);
                h[8 + 2 * q]     = f2fma(d1, ws.x, h[8 + 2 * q]);
                h[8 + 2 * q + 1] = f2fma(d1, ws.y, h[8 + 2 * q + 1]);
            }
        }
        u64 z = pack2(0.0f, 0.0f);
        u64 c0 = z, c1 = z, c2 = z;
        #pragma unroll
        for (int m = 0; m < 16; m++) {
            u64 r = f2relu(h[m]);
            c0 = f2fma(r, cw.w3p[m],      c0);
            c1 = f2fma(r, cw.w3p[16 + m], c1);
            c2 = f2fma(r, cw.w3p[32 + m], c2);
        }
        float lo, hi;
        unpack2(c0, lo, hi); k0 = bq0 + lo + hi;
        unpack2(c1, lo, hi); k1 = bq1 + lo + hi;
        unpack2(c2, lo, hi); k2 = bq2 + lo + hi;
    };

    #pragma unroll 1
    for (int step = 0; step < NSTEP; step++) {
        float s0 = 0.f, s1 = 0.f, s2 = 0.f;
        float a0 = y0, a1 = y1, a2 = y2;

        #pragma unroll 1
        for (int st = 0; st < 4; st++) {
            float k0, k1, k2;
            mlp(a0, a1, a2, k0, k1, k2);
            float cs = (st == 1 || st == 2) ? 2.0f : 1.0f;
            float ca = (st == 2) ? dt : hdt;
            s0 = fmaf(k0, cs, s0); s1 = fmaf(k1, cs, s1); s2 = fmaf(k2, cs, s2);
            a0 = fmaf(k0, ca, y0); a1 = fmaf(k1, ca, y1); a2 = fmaf(k2, ca, y2);
        }
        y0 = fmaf(s0, sx, y0); y1 = fmaf(s1, sx, y1); y2 = fmaf(s2, sx, y2);

        if ((emit_mask >> step) & 1ull) {
            float o = fmaf(y0, wo0, fmaf(y1, wo1, fmaf(y2, wo2, bo)));
            #pragma unroll 1
            for (int s = 0; s < 8; s++) {
                if (ssidx[s] == step) out[s * B_POINTS + p] = o;
            }
        }
    }
}

extern "C" void kernel_launch(void* const* d_in, const int* in_sizes, int n_in,
                              void* d_out, int out_size)
{
    const float* x      = (const float*)d_in[0];
    const float* samples= (const float*)d_in[1];
    const float* w1     = (const float*)d_in[2];
    const float* b1     = (const float*)d_in[3];
    const float* w2     = (const float*)d_in[4];
    const float* b2     = (const float*)d_in[5];
    const float* w3     = (const float*)d_in[6];
    const float* b3     = (const float*)d_in[7];
    const float* w_out  = (const float*)d_in[8];
    const float* b_out  = (const float*)d_in[9];
    float* out = (float*)d_out;

    // Stage transformed weights, then copy into __constant__ (D2D, capturable).
    prep_kernel<<<1, 128>>>(w2, b2, w3);
    void* stage_addr = nullptr;
    cudaGetSymbolAddress(&stage_addr, g_stage);
    cudaMemcpyToSymbolAsync(cw, stage_addr, sizeof(CW), 0,
                            cudaMemcpyDeviceToDevice, 0);

    ode_rk4_kernel<<<NBLOCKS, NTHREADS>>>(x, samples, w1, b1, w2,
                                          b3, w_out, b_out, out);
}